// round 9
// baseline (speedup 1.0000x reference)
#include <cuda_runtime.h>
#include <cuda_fp16.h>
#include <math.h>
#include <stdint.h>

#define MAXN 16
#define HDIM 64
#define DDIM 64
#define HID 40
#define BMAX 65536

// ---------------- device scratch (no allocations allowed) ----------------
__device__ int g_n[BMAX];                  // per-row argmax

// ---------------- helpers ----------------
__device__ __forceinline__ float gelu_tanh(float x) {
    float x3 = x * x * x;
    float t = tanhf(0.7978845608028654f * (x + 0.044715f * x3));
    return 0.5f * x * (1.0f + t);
}
// 1-MUFU gelu: hardware tanh.approx.f32 (sm_75+)
__device__ __forceinline__ float gelu_t(float x) {
    float x2 = x * x;
    float u = x * (0.7978845608f + 0.0356774081f * x2);
    float t;
    asm("tanh.approx.f32 %0, %1;" : "=f"(t) : "f"(u));
    return 0.5f * x * (1.0f + t);
}
// pack two floats -> half2 bits (lo in low 16 bits)
__device__ __forceinline__ uint32_t f2h2(float lo, float hi) {
    uint32_t r;
    asm("cvt.rn.f16x2.f32 %0, %1, %2;" : "=r"(r) : "f"(hi), "f"(lo));
    return r;
}
__device__ __forceinline__ void mma_f16(float& c0, float& c1, float& c2, float& c3,
                                        uint32_t a0, uint32_t a1, uint32_t a2, uint32_t a3,
                                        uint32_t b0, uint32_t b1) {
    asm volatile(
        "mma.sync.aligned.m16n8k16.row.col.f32.f16.f16.f32 "
        "{%0,%1,%2,%3}, {%4,%5,%6,%7}, {%8,%9}, {%0,%1,%2,%3};"
        : "+f"(c0), "+f"(c1), "+f"(c2), "+f"(c3)
        : "r"(a0), "r"(a1), "r"(a2), "r"(a3), "r"(b0), "r"(b1));
}

// ================= sp: size MLP + argmax + mask/batch/n_pred (exact fp32) =================
#define SP_ROWS 128
__global__ void __launch_bounds__(SP_ROWS) sp_kernel(
    const float* __restrict__ z,
    const float* __restrict__ w1, const float* __restrict__ b1,
    const float* __restrict__ w2, const float* __restrict__ b2,
    float* __restrict__ out_npred, float* __restrict__ out_mask,
    float* __restrict__ out_batch) {
    __shared__ float zs[SP_ROWS][65];     // pitch 65: conflict-free zs[tid][k]
    __shared__ float w1s[HDIM * HID];
    __shared__ float w2s[HID * MAXN];
    __shared__ float b1s[HID];
    __shared__ float b2s[MAXN];

    int tid = threadIdx.x;
    int row0 = blockIdx.x * SP_ROWS;

    for (int i = tid; i < HDIM * HID; i += SP_ROWS) w1s[i] = w1[i];
    for (int i = tid; i < HID * MAXN; i += SP_ROWS) w2s[i] = w2[i];
    if (tid < HID)  b1s[tid] = b1[tid];
    if (tid < MAXN) b2s[tid] = b2[tid];
    for (int i = tid; i < SP_ROWS * (HDIM / 4); i += SP_ROWS) {
        int r = i / (HDIM / 4), c4 = i % (HDIM / 4);
        float4 v = ((const float4*)(z + (size_t)(row0 + r) * HDIM))[c4];
        zs[r][c4 * 4 + 0] = v.x;
        zs[r][c4 * 4 + 1] = v.y;
        zs[r][c4 * 4 + 2] = v.z;
        zs[r][c4 * 4 + 3] = v.w;
    }
    __syncthreads();

    int b = row0 + tid;
    float h[HID];
    #pragma unroll
    for (int j4 = 0; j4 < HID / 4; j4++) {
        float4 bv = *(const float4*)&b1s[j4 * 4];
        h[j4 * 4 + 0] = bv.x; h[j4 * 4 + 1] = bv.y;
        h[j4 * 4 + 2] = bv.z; h[j4 * 4 + 3] = bv.w;
    }
    for (int k = 0; k < HDIM; k++) {
        float zk = zs[tid][k];
        const float4* wr = (const float4*)&w1s[k * HID];
        #pragma unroll
        for (int j4 = 0; j4 < HID / 4; j4++) {
            float4 w = wr[j4];
            h[j4 * 4 + 0] += zk * w.x;
            h[j4 * 4 + 1] += zk * w.y;
            h[j4 * 4 + 2] += zk * w.z;
            h[j4 * 4 + 3] += zk * w.w;
        }
    }
    float o[MAXN];
    #pragma unroll
    for (int p4 = 0; p4 < MAXN / 4; p4++) {
        float4 bv = *(const float4*)&b2s[p4 * 4];
        o[p4 * 4 + 0] = bv.x; o[p4 * 4 + 1] = bv.y;
        o[p4 * 4 + 2] = bv.z; o[p4 * 4 + 3] = bv.w;
    }
    #pragma unroll
    for (int j = 0; j < HID; j++) {
        float hj = gelu_tanh(h[j]);
        const float4* wr = (const float4*)&w2s[j * MAXN];
        #pragma unroll
        for (int p4 = 0; p4 < MAXN / 4; p4++) {
            float4 w = wr[p4];
            o[p4 * 4 + 0] += hj * w.x;
            o[p4 * 4 + 1] += hj * w.y;
            o[p4 * 4 + 2] += hj * w.z;
            o[p4 * 4 + 3] += hj * w.w;
        }
    }
    int n = 0; float best = o[0];
    #pragma unroll
    for (int p = 1; p < MAXN; p++)
        if (o[p] > best) { best = o[p]; n = p; }
    g_n[b] = n;

    size_t base = (size_t)b * MAXN;
    #pragma unroll
    for (int p4 = 0; p4 < MAXN / 4; p4++)
        *(float4*)(out_npred + base + p4 * 4) =
            make_float4(o[p4 * 4 + 0], o[p4 * 4 + 1], o[p4 * 4 + 2], o[p4 * 4 + 3]);
    float fb = (float)b;
    #pragma unroll
    for (int p4 = 0; p4 < MAXN / 4; p4++) {
        float4 mv;
        mv.x = (p4 * 4 + 0 < n) ? 1.0f : 0.0f;
        mv.y = (p4 * 4 + 1 < n) ? 1.0f : 0.0f;
        mv.z = (p4 * 4 + 2 < n) ? 1.0f : 0.0f;
        mv.w = (p4 * 4 + 3 < n) ? 1.0f : 0.0f;
        *(float4*)(out_mask + base + p4 * 4) = mv;
        *(float4*)(out_batch + base + p4 * 4) = make_float4(fb, fb, fb, fb);
    }
}

// ================= dec: persistent fp16-MMA fused MLP, 2 CTAs/SM =================
#define DEC_THREADS 256
// dynamic smem layout (float indices)
#define SOFF_PE  0                        // [16][68] = 1088
#define SOFF_ZB  (SOFF_PE + 16 * 68)      // 8 warps * 128 = 1024
#define SOFF_B1  (SOFF_ZB + 1024)         // 64
#define SOFF_B2  (SOFF_B1 + 64)           // 64
#define SOFF_W1H (SOFF_B2 + 64)           // 2304 u32: W1^T half [n][72h]
#define SOFF_W2H (SOFF_W1H + 2304)        // 2304 u32
#define SOFF_HH  (SOFF_W2H + 2304)        // 8 warps * 1152 u32 (also init scratch)
#define DEC_SMEM_FLOATS (SOFF_HH + 8 * 1152)
#define DEC_SMEM_BYTES  (DEC_SMEM_FLOATS * 4)

__global__ void __launch_bounds__(DEC_THREADS, 2) dec_kernel(
    const float* __restrict__ z,
    const float* __restrict__ dw1, const float* __restrict__ db1,
    const float* __restrict__ dw2, const float* __restrict__ db2,
    const float* __restrict__ pw1, const float* __restrict__ pb1,
    const float* __restrict__ pw2, const float* __restrict__ pb2,
    float* __restrict__ out_x, int nstrips) {
    extern __shared__ __align__(16) float smem[];
    float* pe_f = smem + SOFF_PE;          // fp32, pitch 68
    float* zb   = smem + SOFF_ZB;
    float* b1s  = smem + SOFF_B1;
    float* b2s  = smem + SOFF_B2;
    uint32_t* W1h = (uint32_t*)(smem + SOFF_W1H);
    uint32_t* W2h = (uint32_t*)(smem + SOFF_W2H);
    uint32_t* Hh  = (uint32_t*)(smem + SOFF_HH);

    int tid = threadIdx.x;
    int wid = tid >> 5;
    int lane = tid & 31;
    int grp = lane >> 3;                   // careful: defined below properly
    // fragment coords
    grp = lane >> 2;                       // 0..7
    int rem = lane & 3;                    // 0..3

    // ---- one-time prologue ----
    {
        float* hid = (float*)Hh;           // init scratch (overlaps H region)
        for (int i = tid; i < MAXN * HID; i += DEC_THREADS)
            hid[i] = gelu_tanh(pw1[i] + pb1[i % HID]);
        if (tid < 64) { b1s[tid] = db1[tid]; b2s[tid] = db2[tid]; }
        __syncthreads();
        for (int i = tid; i < MAXN * 64; i += DEC_THREADS) {
            int p = i >> 6, d = i & 63;
            float acc = pb2[d];
            #pragma unroll
            for (int j = 0; j < HID; j++) acc += hid[p * HID + j] * pw2[j * 64 + d];
            pe_f[p * 68 + d] = acc;
        }
        for (int i = tid; i < 64 * 64; i += DEC_THREADS) {
            int k = i >> 6, n = i & 63;
            ((__half*)W1h)[n * 72 + k] = __float2half_rn(dw1[i]);
            ((__half*)W2h)[n * 72 + k] = __float2half_rn(dw2[i]);
        }
    }
    __syncthreads();

    uint32_t* Hw = Hh + wid * 1152;        // this warp's H strip, pitch 36 u32
    float* zw = zb + wid * 128;

    int stride = gridDim.x * 8;
    int s = blockIdx.x * 8 + wid;
    if (s >= nstrips) return;

    float4 zcur = ((const float4*)(z + (size_t)s * 128))[lane];
    int ncur0 = g_n[2 * s], ncur1 = g_n[2 * s + 1];

    for (; s < nstrips; s += stride) {
        *(float4*)&zw[lane * 4] = zcur;
        int n0 = ncur0, n1 = ncur1;
        __syncwarp();

        int snext = s + stride;
        if (snext < nstrips) {
            zcur = ((const float4*)(z + (size_t)snext * 128))[lane];
            ncur0 = g_n[2 * snext];
            ncur1 = g_n[2 * snext + 1];
        }

        float C[2][8][4];
        #pragma unroll
        for (int mt = 0; mt < 2; mt++)
            #pragma unroll
            for (int nt = 0; nt < 8; nt++)
                #pragma unroll
                for (int q = 0; q < 4; q++) C[mt][nt][q] = 0.0f;

        // ---- GEMM1: A built inline from z (smem) x pe (smem), W1 half smem ----
        #pragma unroll
        for (int kit = 0; kit < 4; kit++) {
            int kk = kit * 16 + 2 * rem;
            uint32_t bf0[8], bf1[8];
            #pragma unroll
            for (int nt = 0; nt < 8; nt++) {
                int bi = (nt * 8 + grp) * 36 + kit * 8 + rem;
                bf0[nt] = W1h[bi];
                bf1[nt] = W1h[bi + 4];
            }
            // pe fragments (mt-invariant)
            float2 p0lo = *(const float2*)&pe_f[grp * 68 + kk];
            float2 p1lo = *(const float2*)&pe_f[(grp + 8) * 68 + kk];
            float2 p0hi = *(const float2*)&pe_f[grp * 68 + kk + 8];
            float2 p1hi = *(const float2*)&pe_f[(grp + 8) * 68 + kk + 8];
            #pragma unroll
            for (int mt = 0; mt < 2; mt++) {
                float2 zlo = *(const float2*)&zw[mt * 64 + kk];
                float2 zhi = *(const float2*)&zw[mt * 64 + kk + 8];
                uint32_t a0 = f2h2(zlo.x * p0lo.x, zlo.y * p0lo.y);
                uint32_t a1 = f2h2(zlo.x * p1lo.x, zlo.y * p1lo.y);
                uint32_t a2 = f2h2(zhi.x * p0hi.x, zhi.y * p0hi.y);
                uint32_t a3 = f2h2(zhi.x * p1hi.x, zhi.y * p1hi.y);
                #pragma unroll
                for (int nt = 0; nt < 8; nt++)
                    mma_f16(C[mt][nt][0], C[mt][nt][1], C[mt][nt][2], C[mt][nt][3],
                            a0, a1, a2, a3, bf0[nt], bf1[nt]);
            }
        }

        // ---- epilogue1: bias + gelu(tanh.approx) -> half2 H in smem ----
        #pragma unroll
        for (int mt = 0; mt < 2; mt++) {
            #pragma unroll
            for (int nt = 0; nt < 8; nt++) {
                int col = nt * 8 + 2 * rem;
                float bx = b1s[col], by = b1s[col + 1];
                uint32_t h01 = f2h2(gelu_t(C[mt][nt][0] + bx),
                                    gelu_t(C[mt][nt][1] + by));
                uint32_t h23 = f2h2(gelu_t(C[mt][nt][2] + bx),
                                    gelu_t(C[mt][nt][3] + by));
                Hw[(mt * 16 + grp) * 36 + nt * 4 + rem] = h01;
                Hw[(mt * 16 + grp + 8) * 36 + nt * 4 + rem] = h23;
            }
        }
        __syncwarp();

        // ---- GEMM2: H (smem half) @ W2 (smem half) ----
        #pragma unroll
        for (int mt = 0; mt < 2; mt++)
            #pragma unroll
            for (int nt = 0; nt < 8; nt++)
                #pragma unroll
                for (int q = 0; q < 4; q++) C[mt][nt][q] = 0.0f;

        #pragma unroll
        for (int kit = 0; kit < 4; kit++) {
            uint32_t bf0[8], bf1[8];
            #pragma unroll
            for (int nt = 0; nt < 8; nt++) {
                int bi = (nt * 8 + grp) * 36 + kit * 8 + rem;
                bf0[nt] = W2h[bi];
                bf1[nt] = W2h[bi + 4];
            }
            #pragma unroll
            for (int mt = 0; mt < 2; mt++) {
                int ai = (mt * 16 + grp) * 36 + kit * 8 + rem;
                uint32_t a0 = Hw[ai];
                uint32_t a1 = Hw[ai + 8 * 36];
                uint32_t a2 = Hw[ai + 4];
                uint32_t a3 = Hw[ai + 8 * 36 + 4];
                #pragma unroll
                for (int nt = 0; nt < 8; nt++)
                    mma_f16(C[mt][nt][0], C[mt][nt][1], C[mt][nt][2], C[mt][nt][3],
                            a0, a1, a2, a3, bf0[nt], bf1[nt]);
            }
        }

        // ---- epilogue2: bias + mask + store ----
        #pragma unroll
        for (int mt = 0; mt < 2; mt++) {
            int nm = mt ? n1 : n0;
            bool v0 = grp < nm;
            bool v1 = grp + 8 < nm;
            int r0 = mt * 16 + grp;
            float* orow0 = out_x + ((size_t)s * 32 + r0) * DDIM;
            float* orow1 = orow0 + 8 * DDIM;
            #pragma unroll
            for (int nt = 0; nt < 8; nt++) {
                int col = nt * 8 + 2 * rem;
                float bx = b2s[col], by = b2s[col + 1];
                float2 lo, hi;
                lo.x = v0 ? (C[mt][nt][0] + bx) : 0.0f;
                lo.y = v0 ? (C[mt][nt][1] + by) : 0.0f;
                hi.x = v1 ? (C[mt][nt][2] + bx) : 0.0f;
                hi.y = v1 ? (C[mt][nt][3] + by) : 0.0f;
                *(float2*)(orow0 + col) = lo;
                *(float2*)(orow1 + col) = hi;
            }
        }
        __syncwarp();
    }
}

// ================= launch =================
extern "C" void kernel_launch(void* const* d_in, const int* in_sizes, int n_in,
                              void* d_out, int out_size) {
    const float* z      = (const float*)d_in[0];
    const float* sp_w1  = (const float*)d_in[1];
    const float* sp_b1  = (const float*)d_in[2];
    const float* sp_w2  = (const float*)d_in[3];
    const float* sp_b2  = (const float*)d_in[4];
    const float* pe_w1  = (const float*)d_in[5];
    const float* pe_b1  = (const float*)d_in[6];
    const float* pe_w2  = (const float*)d_in[7];
    const float* pe_b2  = (const float*)d_in[8];
    const float* dec_w1 = (const float*)d_in[9];
    const float* dec_b1 = (const float*)d_in[10];
    const float* dec_w2 = (const float*)d_in[11];
    const float* dec_b2 = (const float*)d_in[12];

    int B = in_sizes[0] / HDIM;   // 65536

    float* out = (float*)d_out;
    float* out_x     = out;                               // [B,16,64]
    float* out_mask  = out_x + (size_t)B * MAXN * DDIM;   // [B,16]
    float* out_batch = out_mask + (size_t)B * MAXN;       // [B,16]
    float* out_npred = out_batch + (size_t)B * MAXN;      // [B,16]

    static int nsm = 0;
    if (!nsm) {
        cudaDeviceGetAttribute(&nsm, cudaDevAttrMultiProcessorCount, 0);
        if (nsm <= 0) nsm = 148;
        cudaFuncSetAttribute(dec_kernel, cudaFuncAttributeMaxDynamicSharedMemorySize,
                             DEC_SMEM_BYTES);
    }

    sp_kernel<<<B / SP_ROWS, SP_ROWS>>>(z, sp_w1, sp_b1, sp_w2, sp_b2,
                                        out_npred, out_mask, out_batch);

    int nstrips = B / 2;   // 32768 strips of 32 rows
    dec_kernel<<<nsm * 2, DEC_THREADS, DEC_SMEM_BYTES>>>(
        z, dec_w1, dec_b1, dec_w2, dec_b2,
        pe_w1, pe_b1, pe_w2, pe_b2, out_x, nstrips);
}

// round 10
// speedup vs baseline: 1.0610x; 1.0610x over previous
#include <cuda_runtime.h>
#include <cuda_fp16.h>
#include <math.h>
#include <stdint.h>

#define MAXN 16
#define HDIM 64
#define DDIM 64
#define HID 40
#define BMAX 65536

// ---------------- device scratch (no allocations allowed) ----------------
__device__ int g_n[BMAX];                  // per-row argmax

// ---------------- helpers ----------------
__device__ __forceinline__ float gelu_tanh(float x) {
    float x3 = x * x * x;
    float t = tanhf(0.7978845608028654f * (x + 0.044715f * x3));
    return 0.5f * x * (1.0f + t);
}
// 1-MUFU gelu: hardware tanh.approx.f32
__device__ __forceinline__ float gelu_t(float x) {
    float x2 = x * x;
    float u = x * (0.7978845608f + 0.0356774081f * x2);
    float t;
    asm("tanh.approx.f32 %0, %1;" : "=f"(t) : "f"(u));
    return 0.5f * x * (1.0f + t);
}
// pack two floats -> half2 bits (lo in low 16 bits)
__device__ __forceinline__ uint32_t f2h2(float lo, float hi) {
    uint32_t r;
    asm("cvt.rn.f16x2.f32 %0, %1, %2;" : "=r"(r) : "f"(hi), "f"(lo));
    return r;
}
__device__ __forceinline__ void mma_f16(float& c0, float& c1, float& c2, float& c3,
                                        uint32_t a0, uint32_t a1, uint32_t a2, uint32_t a3,
                                        uint32_t b0, uint32_t b1) {
    asm volatile(
        "mma.sync.aligned.m16n8k16.row.col.f32.f16.f16.f32 "
        "{%0,%1,%2,%3}, {%4,%5,%6,%7}, {%8,%9}, {%0,%1,%2,%3};"
        : "+f"(c0), "+f"(c1), "+f"(c2), "+f"(c3)
        : "r"(a0), "r"(a1), "r"(a2), "r"(a3), "r"(b0), "r"(b1));
}

// ================= sp: size MLP + argmax + mask/batch/n_pred =================
#define SP_ROWS 128
__global__ void __launch_bounds__(SP_ROWS) sp_kernel(
    const float* __restrict__ z,
    const float* __restrict__ w1, const float* __restrict__ b1,
    const float* __restrict__ w2, const float* __restrict__ b2,
    float* __restrict__ out_npred, float* __restrict__ out_mask,
    float* __restrict__ out_batch) {
    __shared__ float zs[SP_ROWS][65];     // pitch 65: conflict-free zs[tid][k]
    __shared__ float w1s[HDIM * HID];
    __shared__ float w2s[HID * MAXN];
    __shared__ float b1s[HID];
    __shared__ float b2s[MAXN];

    int tid = threadIdx.x;
    int row0 = blockIdx.x * SP_ROWS;

    for (int i = tid; i < HDIM * HID; i += SP_ROWS) w1s[i] = w1[i];
    for (int i = tid; i < HID * MAXN; i += SP_ROWS) w2s[i] = w2[i];
    if (tid < HID)  b1s[tid] = b1[tid];
    if (tid < MAXN) b2s[tid] = b2[tid];
    for (int i = tid; i < SP_ROWS * (HDIM / 4); i += SP_ROWS) {
        int r = i / (HDIM / 4), c4 = i % (HDIM / 4);
        float4 v = ((const float4*)(z + (size_t)(row0 + r) * HDIM))[c4];
        zs[r][c4 * 4 + 0] = v.x;
        zs[r][c4 * 4 + 1] = v.y;
        zs[r][c4 * 4 + 2] = v.z;
        zs[r][c4 * 4 + 3] = v.w;
    }
    __syncthreads();

    int b = row0 + tid;
    float h[HID];
    #pragma unroll
    for (int j4 = 0; j4 < HID / 4; j4++) {
        float4 bv = *(const float4*)&b1s[j4 * 4];
        h[j4 * 4 + 0] = bv.x; h[j4 * 4 + 1] = bv.y;
        h[j4 * 4 + 2] = bv.z; h[j4 * 4 + 3] = bv.w;
    }
    for (int k = 0; k < HDIM; k++) {
        float zk = zs[tid][k];
        const float4* wr = (const float4*)&w1s[k * HID];
        #pragma unroll
        for (int j4 = 0; j4 < HID / 4; j4++) {
            float4 w = wr[j4];
            h[j4 * 4 + 0] += zk * w.x;
            h[j4 * 4 + 1] += zk * w.y;
            h[j4 * 4 + 2] += zk * w.z;
            h[j4 * 4 + 3] += zk * w.w;
        }
    }
    float o[MAXN];
    #pragma unroll
    for (int p4 = 0; p4 < MAXN / 4; p4++) {
        float4 bv = *(const float4*)&b2s[p4 * 4];
        o[p4 * 4 + 0] = bv.x; o[p4 * 4 + 1] = bv.y;
        o[p4 * 4 + 2] = bv.z; o[p4 * 4 + 3] = bv.w;
    }
    #pragma unroll
    for (int j = 0; j < HID; j++) {
        float hj = gelu_t(h[j]);          // tanh.approx: ~1e-5 err, norm-aggregate safe
        const float4* wr = (const float4*)&w2s[j * MAXN];
        #pragma unroll
        for (int p4 = 0; p4 < MAXN / 4; p4++) {
            float4 w = wr[p4];
            o[p4 * 4 + 0] += hj * w.x;
            o[p4 * 4 + 1] += hj * w.y;
            o[p4 * 4 + 2] += hj * w.z;
            o[p4 * 4 + 3] += hj * w.w;
        }
    }
    int n = 0; float best = o[0];
    #pragma unroll
    for (int p = 1; p < MAXN; p++)
        if (o[p] > best) { best = o[p]; n = p; }
    g_n[b] = n;

    size_t base = (size_t)b * MAXN;
    #pragma unroll
    for (int p4 = 0; p4 < MAXN / 4; p4++)
        *(float4*)(out_npred + base + p4 * 4) =
            make_float4(o[p4 * 4 + 0], o[p4 * 4 + 1], o[p4 * 4 + 2], o[p4 * 4 + 3]);
    float fb = (float)b;
    #pragma unroll
    for (int p4 = 0; p4 < MAXN / 4; p4++) {
        float4 mv;
        mv.x = (p4 * 4 + 0 < n) ? 1.0f : 0.0f;
        mv.y = (p4 * 4 + 1 < n) ? 1.0f : 0.0f;
        mv.z = (p4 * 4 + 2 < n) ? 1.0f : 0.0f;
        mv.w = (p4 * 4 + 3 < n) ? 1.0f : 0.0f;
        *(float4*)(out_mask + base + p4 * 4) = mv;
        *(float4*)(out_batch + base + p4 * 4) = make_float4(fb, fb, fb, fb);
    }
}

// ================= dec: persistent fp16-MMA, reg-resident H handoff =================
#define DEC_THREADS 256
// dynamic smem layout (float indices)
#define SOFF_PE  0                        // [16][68] fp32 = 1088
#define SOFF_ZB  (SOFF_PE + 16 * 68)      // 8 warps * 128 = 1024 (init scratch too)
#define SOFF_B1  (SOFF_ZB + 1024)         // 64
#define SOFF_B2  (SOFF_B1 + 64)           // 64
#define SOFF_W1F (SOFF_B2 + 64)           // 2048 u32: W1 frags [kit*8+nt][lane] u64
#define SOFF_W2F (SOFF_W1F + 2048)        // 2048 u32
#define DEC_SMEM_FLOATS (SOFF_W2F + 2048)
#define DEC_SMEM_BYTES  (DEC_SMEM_FLOATS * 4)

__global__ void __launch_bounds__(DEC_THREADS, 2) dec_kernel(
    const float* __restrict__ z,
    const float* __restrict__ dw1, const float* __restrict__ db1,
    const float* __restrict__ dw2, const float* __restrict__ db2,
    const float* __restrict__ pw1, const float* __restrict__ pb1,
    const float* __restrict__ pw2, const float* __restrict__ pb2,
    float* __restrict__ out_x, int nstrips) {
    extern __shared__ __align__(16) float smem[];
    float* pe_f = smem + SOFF_PE;          // fp32, pitch 68
    float* zb   = smem + SOFF_ZB;
    float* b1s  = smem + SOFF_B1;
    float* b2s  = smem + SOFF_B2;
    uint32_t* W1f = (uint32_t*)(smem + SOFF_W1F);
    uint32_t* W2f = (uint32_t*)(smem + SOFF_W2F);

    int tid = threadIdx.x;
    int wid = tid >> 5;
    int lane = tid & 31;
    int grp = lane >> 2;                   // 0..7
    int rem = lane & 3;                    // 0..3

    // ---- one-time prologue ----
    {
        float* hid = zb;                   // init scratch (640 <= 1024)
        for (int i = tid; i < MAXN * HID; i += DEC_THREADS)
            hid[i] = gelu_t(pw1[i] + pb1[i % HID]);
        if (tid < 64) { b1s[tid] = db1[tid]; b2s[tid] = db2[tid]; }
        __syncthreads();
        for (int i = tid; i < MAXN * 64; i += DEC_THREADS) {
            int p = i >> 6, d = i & 63;
            float acc = pb2[d];
            #pragma unroll
            for (int j = 0; j < HID; j++) acc += hid[p * HID + j] * pw2[j * 64 + d];
            pe_f[p * 68 + d] = acc;
        }
        __syncthreads();   // hid scratch done before zb reuse
        // W fragments pre-arranged: entry i -> u32 of frag (kit,nt,lane,sel)
        for (int i = tid; i < 2048; i += DEC_THREADS) {
            int sel = i & 1;
            int lane_ = (i >> 1) & 31;
            int ntk = i >> 6;              // kit*8+nt
            int kit = ntk >> 3, nt = ntk & 7;
            int g_ = lane_ >> 2, r_ = lane_ & 3;
            int k = kit * 16 + 2 * r_ + sel * 8;
            int n = nt * 8 + g_;
            W1f[i] = f2h2(dw1[k * 64 + n], dw1[(k + 1) * 64 + n]);
            W2f[i] = f2h2(dw2[k * 64 + n], dw2[(k + 1) * 64 + n]);
        }
    }
    __syncthreads();

    float* zw = zb + wid * 128;

    int stride = gridDim.x * 8;
    int s = blockIdx.x * 8 + wid;
    if (s >= nstrips) return;

    float4 zcur = ((const float4*)(z + (size_t)s * 128))[lane];
    int ncur0 = g_n[2 * s], ncur1 = g_n[2 * s + 1];

    for (; s < nstrips; s += stride) {
        *(float4*)&zw[lane * 4] = zcur;
        int n0 = ncur0, n1 = ncur1;
        __syncwarp();

        int snext = s + stride;
        if (snext < nstrips) {
            zcur = ((const float4*)(z + (size_t)snext * 128))[lane];
            ncur0 = g_n[2 * snext];
            ncur1 = g_n[2 * snext + 1];
        }

        float C[2][8][4];
        // ---- init C with b1 (bias folded into accumulation) ----
        #pragma unroll
        for (int nt = 0; nt < 8; nt++) {
            float2 bv = *(const float2*)&b1s[nt * 8 + 2 * rem];
            #pragma unroll
            for (int mt = 0; mt < 2; mt++) {
                C[mt][nt][0] = bv.x; C[mt][nt][1] = bv.y;
                C[mt][nt][2] = bv.x; C[mt][nt][3] = bv.y;
            }
        }

        // ---- GEMM1: A built inline (z smem x pe smem), W1 frags LDS.64 ----
        #pragma unroll
        for (int kit = 0; kit < 4; kit++) {
            int kk = kit * 16 + 2 * rem;
            uint2 bf[8];
            #pragma unroll
            for (int nt = 0; nt < 8; nt++)
                bf[nt] = *(const uint2*)&W1f[(((kit << 3) + nt) << 6) + (lane << 1)];
            float2 p0lo = *(const float2*)&pe_f[grp * 68 + kk];
            float2 p1lo = *(const float2*)&pe_f[(grp + 8) * 68 + kk];
            float2 p0hi = *(const float2*)&pe_f[grp * 68 + kk + 8];
            float2 p1hi = *(const float2*)&pe_f[(grp + 8) * 68 + kk + 8];
            #pragma unroll
            for (int mt = 0; mt < 2; mt++) {
                float2 zlo = *(const float2*)&zw[mt * 64 + kk];
                float2 zhi = *(const float2*)&zw[mt * 64 + kk + 8];
                uint32_t a0 = f2h2(zlo.x * p0lo.x, zlo.y * p0lo.y);
                uint32_t a1 = f2h2(zlo.x * p1lo.x, zlo.y * p1lo.y);
                uint32_t a2 = f2h2(zhi.x * p0hi.x, zhi.y * p0hi.y);
                uint32_t a3 = f2h2(zhi.x * p1hi.x, zhi.y * p1hi.y);
                #pragma unroll
                for (int nt = 0; nt < 8; nt++)
                    mma_f16(C[mt][nt][0], C[mt][nt][1], C[mt][nt][2], C[mt][nt][3],
                            a0, a1, a2, a3, bf[nt].x, bf[nt].y);
            }
        }

        // ---- epilogue1: gelu -> H fragments IN REGISTERS (C-layout == A-layout) ----
        uint32_t Hf[2][4][4];
        #pragma unroll
        for (int mt = 0; mt < 2; mt++) {
            #pragma unroll
            for (int kit = 0; kit < 4; kit++) {
                int na = 2 * kit, nb = 2 * kit + 1;
                Hf[mt][kit][0] = f2h2(gelu_t(C[mt][na][0]), gelu_t(C[mt][na][1]));
                Hf[mt][kit][1] = f2h2(gelu_t(C[mt][na][2]), gelu_t(C[mt][na][3]));
                Hf[mt][kit][2] = f2h2(gelu_t(C[mt][nb][0]), gelu_t(C[mt][nb][1]));
                Hf[mt][kit][3] = f2h2(gelu_t(C[mt][nb][2]), gelu_t(C[mt][nb][3]));
            }
        }

        // ---- re-init C with b2 ----
        #pragma unroll
        for (int nt = 0; nt < 8; nt++) {
            float2 bv = *(const float2*)&b2s[nt * 8 + 2 * rem];
            #pragma unroll
            for (int mt = 0; mt < 2; mt++) {
                C[mt][nt][0] = bv.x; C[mt][nt][1] = bv.y;
                C[mt][nt][2] = bv.x; C[mt][nt][3] = bv.y;
            }
        }

        // ---- GEMM2: H from registers, W2 frags LDS.64 ----
        #pragma unroll
        for (int kit = 0; kit < 4; kit++) {
            uint2 bf[8];
            #pragma unroll
            for (int nt = 0; nt < 8; nt++)
                bf[nt] = *(const uint2*)&W2f[(((kit << 3) + nt) << 6) + (lane << 1)];
            #pragma unroll
            for (int mt = 0; mt < 2; mt++) {
                #pragma unroll
                for (int nt = 0; nt < 8; nt++)
                    mma_f16(C[mt][nt][0], C[mt][nt][1], C[mt][nt][2], C[mt][nt][3],
                            Hf[mt][kit][0], Hf[mt][kit][1],
                            Hf[mt][kit][2], Hf[mt][kit][3],
                            bf[nt].x, bf[nt].y);
            }
        }

        // ---- epilogue2: mask + store ----
        #pragma unroll
        for (int mt = 0; mt < 2; mt++) {
            int nm = mt ? n1 : n0;
            bool v0 = grp < nm;
            bool v1 = grp + 8 < nm;
            int r0 = mt * 16 + grp;
            float* orow0 = out_x + ((size_t)s * 32 + r0) * DDIM;
            float* orow1 = orow0 + 8 * DDIM;
            #pragma unroll
            for (int nt = 0; nt < 8; nt++) {
                int col = nt * 8 + 2 * rem;
                float2 lo, hi;
                lo.x = v0 ? C[mt][nt][0] : 0.0f;
                lo.y = v0 ? C[mt][nt][1] : 0.0f;
                hi.x = v1 ? C[mt][nt][2] : 0.0f;
                hi.y = v1 ? C[mt][nt][3] : 0.0f;
                *(float2*)(orow0 + col) = lo;
                *(float2*)(orow1 + col) = hi;
            }
        }
        __syncwarp();
    }
}

// ================= launch =================
extern "C" void kernel_launch(void* const* d_in, const int* in_sizes, int n_in,
                              void* d_out, int out_size) {
    const float* z      = (const float*)d_in[0];
    const float* sp_w1  = (const float*)d_in[1];
    const float* sp_b1  = (const float*)d_in[2];
    const float* sp_w2  = (const float*)d_in[3];
    const float* sp_b2  = (const float*)d_in[4];
    const float* pe_w1  = (const float*)d_in[5];
    const float* pe_b1  = (const float*)d_in[6];
    const float* pe_w2  = (const float*)d_in[7];
    const float* pe_b2  = (const float*)d_in[8];
    const float* dec_w1 = (const float*)d_in[9];
    const float* dec_b1 = (const float*)d_in[10];
    const float* dec_w2 = (const float*)d_in[11];
    const float* dec_b2 = (const float*)d_in[12];

    int B = in_sizes[0] / HDIM;   // 65536

    float* out = (float*)d_out;
    float* out_x     = out;                               // [B,16,64]
    float* out_mask  = out_x + (size_t)B * MAXN * DDIM;   // [B,16]
    float* out_batch = out_mask + (size_t)B * MAXN;       // [B,16]
    float* out_npred = out_batch + (size_t)B * MAXN;      // [B,16]

    static int nsm = 0;
    if (!nsm) {
        cudaDeviceGetAttribute(&nsm, cudaDevAttrMultiProcessorCount, 0);
        if (nsm <= 0) nsm = 148;
        cudaFuncSetAttribute(dec_kernel, cudaFuncAttributeMaxDynamicSharedMemorySize,
                             DEC_SMEM_BYTES);
    }

    sp_kernel<<<B / SP_ROWS, SP_ROWS>>>(z, sp_w1, sp_b1, sp_w2, sp_b2,
                                        out_npred, out_mask, out_batch);

    int nstrips = B / 2;   // 32768 strips of 32 rows
    dec_kernel<<<nsm * 2, DEC_THREADS, DEC_SMEM_BYTES>>>(
        z, dec_w1, dec_b1, dec_w2, dec_b2,
        pe_w1, pe_b1, pe_w2, pe_b2, out_x, nstrips);
}

// round 11
// speedup vs baseline: 1.0894x; 1.0268x over previous
#include <cuda_runtime.h>
#include <cuda_fp16.h>
#include <math.h>
#include <stdint.h>

#define MAXN 16
#define HDIM 64
#define DDIM 64
#define HID 40
#define BMAX 65536

// ---------------- device scratch (no allocations allowed) ----------------
__device__ int g_n[BMAX];                  // per-row argmax

// ---------------- helpers ----------------
__device__ __forceinline__ float gelu_tanh(float x) {
    float x3 = x * x * x;
    float t = tanhf(0.7978845608028654f * (x + 0.044715f * x3));
    return 0.5f * x * (1.0f + t);
}
// 1-MUFU gelu: hardware tanh.approx.f32
__device__ __forceinline__ float gelu_t(float x) {
    float x2 = x * x;
    float u = x * (0.7978845608f + 0.0356774081f * x2);
    float t;
    asm("tanh.approx.f32 %0, %1;" : "=f"(t) : "f"(u));
    return 0.5f * x * (1.0f + t);
}
// half2 gelu: u = x*(A + B*x^2); y = 0.5x*(1+tanh(u)) all in f16x2
__device__ __forceinline__ uint32_t gelu_h2(uint32_t xb, __half2 A2, __half2 B2,
                                            __half2 H05) {
    __half2 x = *reinterpret_cast<__half2*>(&xb);
    __half2 x2 = __hmul2(x, x);
    __half2 u = __hmul2(x, __hfma2(B2, x2, A2));
    uint32_t ub = *reinterpret_cast<uint32_t*>(&u);
    uint32_t tb;
    asm("tanh.approx.f16x2 %0, %1;" : "=r"(tb) : "r"(ub));
    __half2 t = *reinterpret_cast<__half2*>(&tb);
    __half2 hx = __hmul2(x, H05);
    __half2 y = __hfma2(hx, t, hx);
    return *reinterpret_cast<uint32_t*>(&y);
}
// pack two floats -> half2 bits (lo in low 16 bits)
__device__ __forceinline__ uint32_t f2h2(float lo, float hi) {
    uint32_t r;
    asm("cvt.rn.f16x2.f32 %0, %1, %2;" : "=r"(r) : "f"(hi), "f"(lo));
    return r;
}
__device__ __forceinline__ void mma_f16(float& c0, float& c1, float& c2, float& c3,
                                        uint32_t a0, uint32_t a1, uint32_t a2, uint32_t a3,
                                        uint32_t b0, uint32_t b1) {
    asm volatile(
        "mma.sync.aligned.m16n8k16.row.col.f32.f16.f16.f32 "
        "{%0,%1,%2,%3}, {%4,%5,%6,%7}, {%8,%9}, {%0,%1,%2,%3};"
        : "+f"(c0), "+f"(c1), "+f"(c2), "+f"(c3)
        : "r"(a0), "r"(a1), "r"(a2), "r"(a3), "r"(b0), "r"(b1));
}

// ================= sp: size MLP + argmax + mask/batch/n_pred =================
#define SP_ROWS 128
__global__ void __launch_bounds__(SP_ROWS) sp_kernel(
    const float* __restrict__ z,
    const float* __restrict__ w1, const float* __restrict__ b1,
    const float* __restrict__ w2, const float* __restrict__ b2,
    float* __restrict__ out_npred, float* __restrict__ out_mask,
    float* __restrict__ out_batch) {
    __shared__ float zs[SP_ROWS][65];
    __shared__ float w1s[HDIM * HID];
    __shared__ float w2s[HID * MAXN];
    __shared__ float b1s[HID];
    __shared__ float b2s[MAXN];

    int tid = threadIdx.x;
    int row0 = blockIdx.x * SP_ROWS;

    for (int i = tid; i < HDIM * HID; i += SP_ROWS) w1s[i] = w1[i];
    for (int i = tid; i < HID * MAXN; i += SP_ROWS) w2s[i] = w2[i];
    if (tid < HID)  b1s[tid] = b1[tid];
    if (tid < MAXN) b2s[tid] = b2[tid];
    for (int i = tid; i < SP_ROWS * (HDIM / 4); i += SP_ROWS) {
        int r = i / (HDIM / 4), c4 = i % (HDIM / 4);
        float4 v = ((const float4*)(z + (size_t)(row0 + r) * HDIM))[c4];
        zs[r][c4 * 4 + 0] = v.x;
        zs[r][c4 * 4 + 1] = v.y;
        zs[r][c4 * 4 + 2] = v.z;
        zs[r][c4 * 4 + 3] = v.w;
    }
    __syncthreads();

    int b = row0 + tid;
    float h[HID];
    #pragma unroll
    for (int j4 = 0; j4 < HID / 4; j4++) {
        float4 bv = *(const float4*)&b1s[j4 * 4];
        h[j4 * 4 + 0] = bv.x; h[j4 * 4 + 1] = bv.y;
        h[j4 * 4 + 2] = bv.z; h[j4 * 4 + 3] = bv.w;
    }
    for (int k = 0; k < HDIM; k++) {
        float zk = zs[tid][k];
        const float4* wr = (const float4*)&w1s[k * HID];
        #pragma unroll
        for (int j4 = 0; j4 < HID / 4; j4++) {
            float4 w = wr[j4];
            h[j4 * 4 + 0] += zk * w.x;
            h[j4 * 4 + 1] += zk * w.y;
            h[j4 * 4 + 2] += zk * w.z;
            h[j4 * 4 + 3] += zk * w.w;
        }
    }
    float o[MAXN];
    #pragma unroll
    for (int p4 = 0; p4 < MAXN / 4; p4++) {
        float4 bv = *(const float4*)&b2s[p4 * 4];
        o[p4 * 4 + 0] = bv.x; o[p4 * 4 + 1] = bv.y;
        o[p4 * 4 + 2] = bv.z; o[p4 * 4 + 3] = bv.w;
    }
    #pragma unroll
    for (int j = 0; j < HID; j++) {
        float hj = gelu_t(h[j]);
        const float4* wr = (const float4*)&w2s[j * MAXN];
        #pragma unroll
        for (int p4 = 0; p4 < MAXN / 4; p4++) {
            float4 w = wr[p4];
            o[p4 * 4 + 0] += hj * w.x;
            o[p4 * 4 + 1] += hj * w.y;
            o[p4 * 4 + 2] += hj * w.z;
            o[p4 * 4 + 3] += hj * w.w;
        }
    }
    int n = 0; float best = o[0];
    #pragma unroll
    for (int p = 1; p < MAXN; p++)
        if (o[p] > best) { best = o[p]; n = p; }
    g_n[b] = n;

    size_t base = (size_t)b * MAXN;
    #pragma unroll
    for (int p4 = 0; p4 < MAXN / 4; p4++)
        __stcs((float4*)(out_npred + base + p4 * 4),
               make_float4(o[p4 * 4 + 0], o[p4 * 4 + 1], o[p4 * 4 + 2], o[p4 * 4 + 3]));
    float fb = (float)b;
    #pragma unroll
    for (int p4 = 0; p4 < MAXN / 4; p4++) {
        float4 mv;
        mv.x = (p4 * 4 + 0 < n) ? 1.0f : 0.0f;
        mv.y = (p4 * 4 + 1 < n) ? 1.0f : 0.0f;
        mv.z = (p4 * 4 + 2 < n) ? 1.0f : 0.0f;
        mv.w = (p4 * 4 + 3 < n) ? 1.0f : 0.0f;
        __stcs((float4*)(out_mask + base + p4 * 4), mv);
        __stcs((float4*)(out_batch + base + p4 * 4), make_float4(fb, fb, fb, fb));
    }
}

// ================= dec: persistent fp16-MMA, reg H handoff, STG.128 epilogue ======
#define DEC_THREADS 256
// dynamic smem layout (float indices)
#define SOFF_PE  0                        // [16][68] fp32 = 1088
#define SOFF_ZB  (SOFF_PE + 16 * 68)      // 8 warps * 128 = 1024 (init scratch too)
#define SOFF_B1  (SOFF_ZB + 1024)         // 64
#define SOFF_B2  (SOFF_B1 + 64)           // 64 (PERMUTED b2)
#define SOFF_W1F (SOFF_B2 + 64)           // 2048 u32: W1 frags [kit*8+nt][lane]
#define SOFF_W2F (SOFF_W1F + 2048)        // 2048 u32 (PERMUTED cols)
#define DEC_SMEM_FLOATS (SOFF_W2F + 2048)
#define DEC_SMEM_BYTES  (DEC_SMEM_FLOATS * 4)

__global__ void __launch_bounds__(DEC_THREADS, 2) dec_kernel(
    const float* __restrict__ z,
    const float* __restrict__ dw1, const float* __restrict__ db1,
    const float* __restrict__ dw2, const float* __restrict__ db2,
    const float* __restrict__ pw1, const float* __restrict__ pb1,
    const float* __restrict__ pw2, const float* __restrict__ pb2,
    float* __restrict__ out_x, int nstrips) {
    extern __shared__ __align__(16) float smem[];
    float* pe_f = smem + SOFF_PE;          // fp32, pitch 68
    float* zb   = smem + SOFF_ZB;
    float* b1s  = smem + SOFF_B1;
    float* b2p  = smem + SOFF_B2;          // permuted
    uint32_t* W1f = (uint32_t*)(smem + SOFF_W1F);
    uint32_t* W2f = (uint32_t*)(smem + SOFF_W2F);

    int tid = threadIdx.x;
    int wid = tid >> 5;
    int lane = tid & 31;
    int grp = lane >> 2;                   // 0..7
    int rem = lane & 3;                    // 0..3

    // ---- one-time prologue ----
    {
        float* hid = zb;                   // init scratch (640 <= 1024)
        for (int i = tid; i < MAXN * HID; i += DEC_THREADS)
            hid[i] = gelu_t(pw1[i] + pb1[i % HID]);
        if (tid < 64) {
            b1s[tid] = db1[tid];
            // b2 permuted: b2p[j] = b2[f(j)], f(j)=16*((j&7)>>1)+2*(j>>3)+(j&1)
            int fc = 16 * ((tid & 7) >> 1) + 2 * (tid >> 3) + (tid & 1);
            b2p[tid] = db2[fc];
        }
        __syncthreads();
        for (int i = tid; i < MAXN * 64; i += DEC_THREADS) {
            int p = i >> 6, d = i & 63;
            float acc = pb2[d];
            #pragma unroll
            for (int j = 0; j < HID; j++) acc += hid[p * HID + j] * pw2[j * 64 + d];
            pe_f[p * 68 + d] = acc;
        }
        __syncthreads();   // hid scratch done before zb reuse
        for (int i = tid; i < 2048; i += DEC_THREADS) {
            int sel = i & 1;
            int lane_ = (i >> 1) & 31;
            int ntk = i >> 6;              // kit*8+nt
            int kit = ntk >> 3, nt = ntk & 7;
            int g_ = lane_ >> 2, r_ = lane_ & 3;
            int k = kit * 16 + 2 * r_ + sel * 8;
            int n = nt * 8 + g_;
            W1f[i] = f2h2(dw1[k * 64 + n], dw1[(k + 1) * 64 + n]);
            int fc = 16 * ((n & 7) >> 1) + 2 * (n >> 3) + (n & 1);
            W2f[i] = f2h2(dw2[k * 64 + fc], dw2[(k + 1) * 64 + fc]);
        }
    }
    __syncthreads();

    const __half2 A2  = __float2half2_rn(0.7978845608f);
    const __half2 B2  = __float2half2_rn(0.0356774081f);
    const __half2 H05 = __float2half2_rn(0.5f);

    float* zw = zb + wid * 128;

    int stride = gridDim.x * 8;
    int s = blockIdx.x * 8 + wid;
    if (s >= nstrips) return;

    float4 zcur = ((const float4*)(z + (size_t)s * 128))[lane];
    int ncur0 = g_n[2 * s], ncur1 = g_n[2 * s + 1];

    for (; s < nstrips; s += stride) {
        *(float4*)&zw[lane * 4] = zcur;
        int n0 = ncur0, n1 = ncur1;
        __syncwarp();

        int snext = s + stride;
        if (snext < nstrips) {
            zcur = ((const float4*)(z + (size_t)snext * 128))[lane];
            ncur0 = g_n[2 * snext];
            ncur1 = g_n[2 * snext + 1];
        }

        float C[2][8][4];
        // ---- init C with b1 ----
        #pragma unroll
        for (int nt = 0; nt < 8; nt++) {
            float2 bv = *(const float2*)&b1s[nt * 8 + 2 * rem];
            #pragma unroll
            for (int mt = 0; mt < 2; mt++) {
                C[mt][nt][0] = bv.x; C[mt][nt][1] = bv.y;
                C[mt][nt][2] = bv.x; C[mt][nt][3] = bv.y;
            }
        }

        // ---- GEMM1: A inline (z x pe fp32 -> h2), W1 frags LDS.64 ----
        #pragma unroll
        for (int kit = 0; kit < 4; kit++) {
            int kk = kit * 16 + 2 * rem;
            uint2 bf[8];
            #pragma unroll
            for (int nt = 0; nt < 8; nt++)
                bf[nt] = *(const uint2*)&W1f[(((kit << 3) + nt) << 6) + (lane << 1)];
            float2 p0lo = *(const float2*)&pe_f[grp * 68 + kk];
            float2 p1lo = *(const float2*)&pe_f[(grp + 8) * 68 + kk];
            float2 p0hi = *(const float2*)&pe_f[grp * 68 + kk + 8];
            float2 p1hi = *(const float2*)&pe_f[(grp + 8) * 68 + kk + 8];
            #pragma unroll
            for (int mt = 0; mt < 2; mt++) {
                float2 zlo = *(const float2*)&zw[mt * 64 + kk];
                float2 zhi = *(const float2*)&zw[mt * 64 + kk + 8];
                uint32_t a0 = f2h2(zlo.x * p0lo.x, zlo.y * p0lo.y);
                uint32_t a1 = f2h2(zlo.x * p1lo.x, zlo.y * p1lo.y);
                uint32_t a2 = f2h2(zhi.x * p0hi.x, zhi.y * p0hi.y);
                uint32_t a3 = f2h2(zhi.x * p1hi.x, zhi.y * p1hi.y);
                #pragma unroll
                for (int nt = 0; nt < 8; nt++)
                    mma_f16(C[mt][nt][0], C[mt][nt][1], C[mt][nt][2], C[mt][nt][3],
                            a0, a1, a2, a3, bf[nt].x, bf[nt].y);
            }
        }

        // ---- epilogue1: half2 gelu -> H fragments in registers ----
        uint32_t Hf[2][4][4];
        #pragma unroll
        for (int mt = 0; mt < 2; mt++) {
            #pragma unroll
            for (int kit = 0; kit < 4; kit++) {
                int na = 2 * kit, nb = 2 * kit + 1;
                Hf[mt][kit][0] = gelu_h2(f2h2(C[mt][na][0], C[mt][na][1]), A2, B2, H05);
                Hf[mt][kit][1] = gelu_h2(f2h2(C[mt][na][2], C[mt][na][3]), A2, B2, H05);
                Hf[mt][kit][2] = gelu_h2(f2h2(C[mt][nb][0], C[mt][nb][1]), A2, B2, H05);
                Hf[mt][kit][3] = gelu_h2(f2h2(C[mt][nb][2], C[mt][nb][3]), A2, B2, H05);
            }
        }

        // ---- re-init C with permuted b2 ----
        #pragma unroll
        for (int nt = 0; nt < 8; nt++) {
            float2 bv = *(const float2*)&b2p[nt * 8 + 2 * rem];
            #pragma unroll
            for (int mt = 0; mt < 2; mt++) {
                C[mt][nt][0] = bv.x; C[mt][nt][1] = bv.y;
                C[mt][nt][2] = bv.x; C[mt][nt][3] = bv.y;
            }
        }

        // ---- GEMM2: H from registers, permuted W2 frags ----
        #pragma unroll
        for (int kit = 0; kit < 4; kit++) {
            uint2 bf[8];
            #pragma unroll
            for (int nt = 0; nt < 8; nt++)
                bf[nt] = *(const uint2*)&W2f[(((kit << 3) + nt) << 6) + (lane << 1)];
            #pragma unroll
            for (int mt = 0; mt < 2; mt++) {
                #pragma unroll
                for (int nt = 0; nt < 8; nt++)
                    mma_f16(C[mt][nt][0], C[mt][nt][1], C[mt][nt][2], C[mt][nt][3],
                            Hf[mt][kit][0], Hf[mt][kit][1],
                            Hf[mt][kit][2], Hf[mt][kit][3],
                            bf[nt].x, bf[nt].y);
            }
        }

        // ---- epilogue2: thread owns cols [16rem,16rem+16) -> 4x STG.128 per row ----
        #pragma unroll
        for (int mt = 0; mt < 2; mt++) {
            int nm = mt ? n1 : n0;
            bool v0 = grp < nm;
            bool v1 = grp + 8 < nm;
            int r0 = mt * 16 + grp;
            float* orow0 = out_x + ((size_t)s * 32 + r0) * DDIM + 16 * rem;
            float* orow1 = orow0 + 8 * DDIM;
            #pragma unroll
            for (int t = 0; t < 4; t++) {
                int na = 2 * t, nb = 2 * t + 1;
                float4 lo, hi;
                lo.x = v0 ? C[mt][na][0] : 0.0f;
                lo.y = v0 ? C[mt][na][1] : 0.0f;
                lo.z = v0 ? C[mt][nb][0] : 0.0f;
                lo.w = v0 ? C[mt][nb][1] : 0.0f;
                hi.x = v1 ? C[mt][na][2] : 0.0f;
                hi.y = v1 ? C[mt][na][3] : 0.0f;
                hi.z = v1 ? C[mt][nb][2] : 0.0f;
                hi.w = v1 ? C[mt][nb][3] : 0.0f;
                __stcs((float4*)(orow0 + 4 * t), lo);
                __stcs((float4*)(orow1 + 4 * t), hi);
            }
        }
        __syncwarp();
    }
}

// ================= launch =================
extern "C" void kernel_launch(void* const* d_in, const int* in_sizes, int n_in,
                              void* d_out, int out_size) {
    const float* z      = (const float*)d_in[0];
    const float* sp_w1  = (const float*)d_in[1];
    const float* sp_b1  = (const float*)d_in[2];
    const float* sp_w2  = (const float*)d_in[3];
    const float* sp_b2  = (const float*)d_in[4];
    const float* pe_w1  = (const float*)d_in[5];
    const float* pe_b1  = (const float*)d_in[6];
    const float* pe_w2  = (const float*)d_in[7];
    const float* pe_b2  = (const float*)d_in[8];
    const float* dec_w1 = (const float*)d_in[9];
    const float* dec_b1 = (const float*)d_in[10];
    const float* dec_w2 = (const float*)d_in[11];
    const float* dec_b2 = (const float*)d_in[12];

    int B = in_sizes[0] / HDIM;   // 65536

    float* out = (float*)d_out;
    float* out_x     = out;                               // [B,16,64]
    float* out_mask  = out_x + (size_t)B * MAXN * DDIM;   // [B,16]
    float* out_batch = out_mask + (size_t)B * MAXN;       // [B,16]
    float* out_npred = out_batch + (size_t)B * MAXN;      // [B,16]

    static int nsm = 0;
    if (!nsm) {
        cudaDeviceGetAttribute(&nsm, cudaDevAttrMultiProcessorCount, 0);
        if (nsm <= 0) nsm = 148;
        cudaFuncSetAttribute(dec_kernel, cudaFuncAttributeMaxDynamicSharedMemorySize,
                             DEC_SMEM_BYTES);
    }

    sp_kernel<<<B / SP_ROWS, SP_ROWS>>>(z, sp_w1, sp_b1, sp_w2, sp_b2,
                                        out_npred, out_mask, out_batch);

    int nstrips = B / 2;   // 32768 strips of 32 rows
    dec_kernel<<<nsm * 2, DEC_THREADS, DEC_SMEM_BYTES>>>(
        z, dec_w1, dec_b1, dec_w2, dec_b2,
        pe_w1, pe_b1, pe_w2, pe_b2, out_x, nstrips);
}